// round 15
// baseline (speedup 1.0000x reference)
#include <cuda_runtime.h>
#include <math.h>

#define NB    32
#define CC    64
#define TT    256
#define VV    25
#define ICH   16
#define NSUB  3
#define TV    (TT*VV)      // 6400
#define CTVSZ (CC*TV)      // 409600
#define KATT  (ICH*TT)     // 4096

// -------- scratch (device globals; no allocation) --------
__device__ float g_a[NSUB*NB*ICH*TV];
__device__ float g_b[NSUB*NB*ICH*TV];
__device__ float g_att[NSUB*NB*VV*VV];
__device__ float g_gcn[NB*CTVSZ];
__device__ float g_msg[NB*CTVSZ];
__device__ float g_twT[9*CC*CC];            // transposed tcn weights [kk][o][c] (built in k1)
__device__ float g_scorep[NSUB*NB*8*VV*VV]; // split-K partial scores

// -------- packed f32x2 helpers --------
__device__ __forceinline__ void ffma2(unsigned long long &d,
                                      const unsigned long long a,
                                      const unsigned long long b) {
    asm("fma.rn.f32x2 %0, %1, %2, %0;" : "+l"(d) : "l"(a), "l"(b));
}
__device__ __forceinline__ float f2sum(unsigned long long v) {
    return __uint_as_float((unsigned)v) + __uint_as_float((unsigned)(v >> 32));
}
__device__ __forceinline__ unsigned long long fpack2(float x) {
    const unsigned u = __float_as_uint(x);
    return ((unsigned long long)u << 32) | u;
}
__device__ __forceinline__ float f2lo(unsigned long long v) {
    return __uint_as_float((unsigned)v);
}
__device__ __forceinline__ float f2hi(unsigned long long v) {
    return __uint_as_float((unsigned)(v >> 32));
}

// ============================================================
// K1: a = conv_a(h), b = conv_b(h) (R6 proven form) + side-work:
// blockIdx.y==0 blocks build g_twT (tw[o][c][kk] -> [kk][o][c]).
// ============================================================
__global__ void __launch_bounds__(256) k1_ab(
    const float* __restrict__ h,
    const float* __restrict__ caw, const float* __restrict__ cab,
    const float* __restrict__ cbw, const float* __restrict__ cbb,
    const float* __restrict__ tw)
{
    __shared__ float hs[CC*64];
    __shared__ float wgt[96*CC];
    __shared__ float bias[96];
    const int n   = blockIdx.y;
    const int tv0 = blockIdx.x * 64;
    const int tid = threadIdx.x;

    // side-work: build g_twT (one-off, distributed over the 100 y==0 blocks)
    if (n == 0) {
        const int base = blockIdx.x * 369;
        for (int t = tid; t < 369; t += 256) {
            const int idx = base + t;
            if (idx < 9*CC*CC) {
                const int kk = idx / (CC*CC), oc = idx % (CC*CC);
                g_twT[idx] = tw[oc*9 + kk];
            }
        }
    }

    const float* hb = h + (size_t)n*CTVSZ + tv0;
    for (int idx = tid; idx < CC*16; idx += 256) {
        const int c = idx >> 4, q = idx & 15;
        reinterpret_cast<float4*>(hs)[c*16 + q] =
            reinterpret_cast<const float4*>(hb + (size_t)c*TV)[q];
    }
    for (int idx = tid; idx < 48*CC/4; idx += 256) {
        reinterpret_cast<float4*>(wgt)[idx] = reinterpret_cast<const float4*>(caw)[idx];
        reinterpret_cast<float4*>(wgt + 48*CC)[idx] = reinterpret_cast<const float4*>(cbw)[idx];
    }
    if (tid < 48) { bias[tid] = cab[tid]; bias[48 + tid] = cbb[tid]; }
    __syncthreads();

    const int og = tid >> 4;
    const int cg = tid & 15;
    float acc[6][4];
    #pragma unroll
    for (int i = 0; i < 6; i++)
        #pragma unroll
        for (int j = 0; j < 4; j++) acc[i][j] = 0.f;

    #pragma unroll 4
    for (int c = 0; c < CC; c++) {
        float ir[4], wr[6];
        #pragma unroll
        for (int j = 0; j < 4; j++) ir[j] = hs[c*64 + cg + 16*j];
        #pragma unroll
        for (int i = 0; i < 6; i++) wr[i] = wgt[(og + 16*i)*CC + c];
        #pragma unroll
        for (int i = 0; i < 6; i++)
            #pragma unroll
            for (int j = 0; j < 4; j++) acc[i][j] += wr[i]*ir[j];
    }

    #pragma unroll
    for (int i = 0; i < 6; i++) {
        const int r = og + 16*i;
        const int conv = r / 48;
        const int sic  = r % 48;
        const int s  = sic >> 4;
        const int ic = sic & 15;
        float* dst = conv ? g_b : g_a;
        const size_t base = ((size_t)(s*NB + n)*ICH + ic)*TV + tv0;
        const float bb = bias[r];
        #pragma unroll
        for (int j = 0; j < 4; j++)
            dst[base + cg + 16*j] = acc[i][j] + bb;
    }
}

// ============================================================
// K2a: split-K attention partial scores. grid (96, 8).
// ============================================================
#define K2ASL  512
#define K2ASTR 520
#define K2A_SMEM (2*25*K2ASTR*4)   // 104,000 B

__global__ void __launch_bounds__(800) k2a_score()
{
    extern __shared__ float sm2a[];
    float* sat = sm2a;
    float* sbt = sm2a + 25*K2ASTR;
    const int sn  = blockIdx.x;
    const int sl  = blockIdx.y;
    const int k0  = sl * K2ASL;
    const int tid = threadIdx.x;
    const float* ab  = g_a + (size_t)sn*KATT*VV;
    const float* bbp = g_b + (size_t)sn*KATT*VV;

    for (int idx = tid; idx < K2ASL*VV; idx += 800) {
        const int r = idx / VV, vv = idx - r*VV;
        sat[vv*K2ASTR + r] = ab[(size_t)k0*VV + idx];
        sbt[vv*K2ASTR + r] = bbp[(size_t)k0*VV + idx];
    }
    __syncthreads();

    const int warp = tid >> 5;
    const int lane = tid & 31;
    const int v0 = (warp / 5) * 5;
    const int w0 = (warp % 5) * 5;

    float acc[5][5];
    #pragma unroll
    for (int x = 0; x < 5; x++)
        #pragma unroll
        for (int y = 0; y < 5; y++) acc[x][y] = 0.f;

    #pragma unroll 4
    for (int i = 0; i < K2ASL/32; i++) {
        const int k = lane + 32*i;
        float av[5], bv[5];
        #pragma unroll
        for (int x = 0; x < 5; x++) av[x] = sat[(v0 + x)*K2ASTR + k];
        #pragma unroll
        for (int y = 0; y < 5; y++) bv[y] = sbt[(w0 + y)*K2ASTR + k];
        #pragma unroll
        for (int x = 0; x < 5; x++)
            #pragma unroll
            for (int y = 0; y < 5; y++) acc[x][y] += av[x]*bv[y];
    }

    #pragma unroll
    for (int off = 16; off > 0; off >>= 1)
        #pragma unroll
        for (int x = 0; x < 5; x++)
            #pragma unroll
            for (int y = 0; y < 5; y++)
                acc[x][y] += __shfl_down_sync(0xffffffffu, acc[x][y], off);

    if (lane == 0) {
        float* dst = g_scorep + ((size_t)sn*8 + sl)*VV*VV;
        #pragma unroll
        for (int x = 0; x < 5; x++)
            #pragma unroll
            for (int y = 0; y < 5; y++)
                dst[(v0 + x)*VV + w0 + y] = acc[x][y];
    }
}

// ============================================================
// K2b: reduce split-K partials + softmax + Aeff -> g_att
// ============================================================
__global__ void __launch_bounds__(640) k2b_soft(
    const float* __restrict__ Amat, const float* __restrict__ PA)
{
    __shared__ float score[VV*VV];
    __shared__ float wm[VV], wi[VV];
    const int sn  = blockIdx.x;
    const int tid = threadIdx.x;

    if (tid < VV*VV) {
        const float* sp = g_scorep + (size_t)sn*8*VV*VV + tid;
        float sum = 0.f;
        #pragma unroll
        for (int sl = 0; sl < 8; sl++) sum += sp[sl*VV*VV];
        score[tid] = sum * (1.f/4096.f);
    }
    __syncthreads();

    if (tid < VV) {
        const int ww = tid;
        float m = -1e30f;
        for (int vv = 0; vv < VV; vv++) m = fmaxf(m, score[vv*VV + ww]);
        float sum = 0.f;
        for (int vv = 0; vv < VV; vv++) sum += expf(score[vv*VV + ww] - m);
        wm[ww] = m; wi[ww] = 1.f/sum;
    }
    __syncthreads();

    if (tid < VV*VV) {
        const int vv = tid / VV, ww = tid % VV;
        const int s = sn / NB;
        const float e = expf(score[tid] - wm[ww])*wi[ww]
                      + Amat[(s*VV + vv)*VV + ww] + PA[(s*VV + vv)*VV + ww];
        g_att[(size_t)sn*VV*VV + tid] = e;
    }
}

// ============================================================
// K3 v3: column-packed f32x2 gcn. conv_d weights staged RAW
// (coalesced [o][c]) and read as warp-uniform broadcast scalars.
// Launched 4th -> profiled by ncu.
// ============================================================
#define K3HST 68
#define K3HW  175
#define K3_SMEM ((K3HW*K3HST + CC*128 + CC*CC + 640)*4)   // 99,312 B

__global__ void __launch_bounds__(512, 2) k3_gcn(
    const float* __restrict__ h,
    const float* __restrict__ cdw, const float* __restrict__ cdb,
    const float* __restrict__ bng, const float* __restrict__ bnb,
    const float* __restrict__ bnm, const float* __restrict__ bnv)
{
    extern __shared__ float sm3[];
    float* hst  = sm3;                        // [row][c] stride 68
    float* zs   = sm3 + K3HW*K3HST;           // [c][j]  64 x 128
    float* cdwS = zs + CC*128;                // [o][c] raw layout
    float* atts = cdwS + CC*CC;               // 625
    const int n   = blockIdx.y;
    const int j0  = blockIdx.x * 128;
    const int t0  = j0 / 25;
    const int jwb = t0 * 25;
    const int W   = ((j0 + 127)/25 + 1)*25 - jwb;
    const int tid = threadIdx.x;

    for (int idx = tid; idx < CC*W; idx += 512) {
        const int c = idx / W, r = idx - c*W;
        hst[r*K3HST + c] = h[(size_t)n*CTVSZ + (size_t)c*TV + jwb + r];
    }

    const int jg = tid & 31;
    const int cg = tid >> 5;
    int trow[4], wv[4];
    #pragma unroll
    for (int jj = 0; jj < 4; jj++) {
        const int jglob = j0 + jg*4 + jj;
        trow[jj] = (jglob/25)*25 - jwb;
        wv[jj]   = jglob % 25;
    }

    unsigned long long acc2[4][2];
    #pragma unroll
    for (int i = 0; i < 4; i++) { acc2[i][0] = 0ull; acc2[i][1] = 0ull; }

    for (int s = 0; s < NSUB; s++) {
        __syncthreads();
        for (int idx = tid; idx < VV*VV; idx += 512)
            atts[idx] = g_att[(size_t)(s*NB + n)*VV*VV + idx];
        for (int idx = tid; idx < CC*CC/4; idx += 512)
            reinterpret_cast<float4*>(cdwS)[idx] =
                reinterpret_cast<const float4*>(cdw + s*CC*CC)[idx];
        __syncthreads();

        // z-phase
        {
            const int c0 = cg*4;
            unsigned long long zacc[4][2];
            #pragma unroll
            for (int jj = 0; jj < 4; jj++) { zacc[jj][0]=0ull; zacc[jj][1]=0ull; }
            #pragma unroll 5
            for (int v = 0; v < VV; v++) {
                #pragma unroll
                for (int jj = 0; jj < 4; jj++) {
                    const ulonglong2 h2 = *reinterpret_cast<const ulonglong2*>(
                        &hst[(trow[jj] + v)*K3HST + c0]);
                    const unsigned long long a2 = fpack2(atts[v*VV + wv[jj]]);
                    ffma2(zacc[jj][0], h2.x, a2);
                    ffma2(zacc[jj][1], h2.y, a2);
                }
            }
            #pragma unroll
            for (int cc = 0; cc < 4; cc++) {
                const int p = cc >> 1, lo = !(cc & 1);
                float4 zv;
                zv.x = lo ? f2lo(zacc[0][p]) : f2hi(zacc[0][p]);
                zv.y = lo ? f2lo(zacc[1][p]) : f2hi(zacc[1][p]);
                zv.z = lo ? f2lo(zacc[2][p]) : f2hi(zacc[2][p]);
                zv.w = lo ? f2lo(zacc[3][p]) : f2hi(zacc[3][p]);
                *reinterpret_cast<float4*>(&zs[(c0 + cc)*128 + jg*4]) = zv;
            }
        }
        __syncthreads();

        // conv_d: weights as warp-uniform broadcast scalars from raw [o][c]
        #pragma unroll 4
        for (int c = 0; c < CC; c++) {
            const ulonglong2 z2 = *reinterpret_cast<const ulonglong2*>(
                                      &zs[c*128 + jg*4]);
            unsigned long long wp;
            wp = fpack2(cdwS[(cg*4 + 0)*CC + c]);
            ffma2(acc2[0][0], z2.x, wp); ffma2(acc2[0][1], z2.y, wp);
            wp = fpack2(cdwS[(cg*4 + 1)*CC + c]);
            ffma2(acc2[1][0], z2.x, wp); ffma2(acc2[1][1], z2.y, wp);
            wp = fpack2(cdwS[(cg*4 + 2)*CC + c]);
            ffma2(acc2[2][0], z2.x, wp); ffma2(acc2[2][1], z2.y, wp);
            wp = fpack2(cdwS[(cg*4 + 3)*CC + c]);
            ffma2(acc2[3][0], z2.x, wp); ffma2(acc2[3][1], z2.y, wp);
        }
    }

    #pragma unroll
    for (int i = 0; i < 4; i++) {
        const int o = cg*4 + i;
        const float scale = bng[o] * rsqrtf(bnv[o] + 1e-5f);
        const float mm = bnm[o], bb = bnb[o];
        const float bsum = cdb[o] + cdb[CC + o] + cdb[2*CC + o];
        float y[4];
        y[0] = f2lo(acc2[i][0]); y[1] = f2hi(acc2[i][0]);
        y[2] = f2lo(acc2[i][1]); y[3] = f2hi(acc2[i][1]);
        float4 outv;
        float* po = &outv.x;
        #pragma unroll
        for (int jj = 0; jj < 4; jj++) {
            const int r = j0 + jg*4 + jj - jwb;
            const float val = (y[jj] + bsum - mm)*scale + bb + hst[r*K3HST + o];
            po[jj] = fmaxf(val, 0.f);
        }
        *reinterpret_cast<float4*>(
            &g_gcn[(size_t)n*CTVSZ + (size_t)o*TV + j0 + jg*4]) = outv;
    }
}

// ============================================================
// K4: tcn with smem weight staging (proven R12 version)
// ============================================================
#define K4W   128
#define K4IN  328
#define K4STR 68
#define K4_SMEM ((K4IN*K4STR + CC*CC)*4)   // 105,600 B

__global__ void __launch_bounds__(256, 2) k4_tcn(
    const float* __restrict__ h,
    const float* __restrict__ tb,
    const float* __restrict__ bng, const float* __restrict__ bnb,
    const float* __restrict__ bnm, const float* __restrict__ bnv)
{
    extern __shared__ float sm4[];
    float* in = sm4;
    float* wk = sm4 + K4IN*K4STR;
    const int n   = blockIdx.y;
    const int tv0 = blockIdx.x * K4W;
    const int tid = threadIdx.x;

    for (int idx = tid; idx < CC*K4IN; idx += 256) {
        const int c = idx / K4IN, j = idx % K4IN;
        const int gtv = tv0 - 100 + j;
        const float v = (gtv >= 0 && gtv < TV)
                        ? g_gcn[(size_t)n*CTVSZ + (size_t)c*TV + gtv] : 0.f;
        in[j*K4STR + c] = v;
    }

    const int og   = tid >> 5;
    const int colg = tid & 31;

    unsigned long long acc2[8][4];
    #pragma unroll
    for (int i = 0; i < 8; i++)
        #pragma unroll
        for (int q = 0; q < 4; q++) acc2[i][q] = 0ull;

    for (int kk = 0; kk < 9; kk++) {
        __syncthreads();
        for (int idx = tid; idx < CC*CC/4; idx += 256)
            reinterpret_cast<float4*>(wk)[idx] =
                reinterpret_cast<const float4*>(g_twT + kk*CC*CC)[idx];
        __syncthreads();

        #pragma unroll 2
        for (int c4 = 0; c4 < CC; c4 += 4) {
            ulonglong2 ir[4];
            #pragma unroll
            for (int q = 0; q < 4; q++)
                ir[q] = *reinterpret_cast<const ulonglong2*>(
                            &in[(colg + 32*q + 25*kk)*K4STR + c4]);
            #pragma unroll
            for (int i = 0; i < 8; i++) {
                const ulonglong2 w = *reinterpret_cast<const ulonglong2*>(
                                         &wk[(og*8 + i)*CC + c4]);
                #pragma unroll
                for (int q = 0; q < 4; q++) {
                    ffma2(acc2[i][q], w.x, ir[q].x);
                    ffma2(acc2[i][q], w.y, ir[q].y);
                }
            }
        }
    }

    #pragma unroll
    for (int i = 0; i < 8; i++) {
        const int o = og*8 + i;
        const float scale = bng[o]*rsqrtf(bnv[o] + 1e-5f);
        const float bbias = tb[o], mm = bnm[o], bb2 = bnb[o];
        #pragma unroll
        for (int q = 0; q < 4; q++) {
            const int col = colg + 32*q;
            float val = (f2sum(acc2[i][q]) + bbias - mm)*scale + bb2;
            val += h[(size_t)n*CTVSZ + (size_t)o*TV + tv0 + col];
            g_msg[(size_t)n*CTVSZ + (size_t)o*TV + tv0 + col] = fmaxf(val, 0.f);
        }
    }
}

// ============================================================
// K5: GRU with smem weight staging (proven R12/R9 version)
// ============================================================
#define K5XSTR 132
#define K5_SMEM ((64*K5XSTR + CC*128 + 2*CC*64)*4)   // 99,328 B

__global__ void __launch_bounds__(256, 2) k5_gru(
    const float* __restrict__ feat, const float* __restrict__ hid,
    const float* __restrict__ Wir, const float* __restrict__ Whr,
    const float* __restrict__ Wii, const float* __restrict__ Whi,
    const float* __restrict__ Win, const float* __restrict__ Whh,
    const float* __restrict__ bir, const float* __restrict__ bii,
    const float* __restrict__ bin, float* __restrict__ out)
{
    extern __shared__ float sm5[];
    float* xs = sm5;
    float* ws = sm5 + 64*K5XSTR;
    float* rs = ws + CC*128;
    float* zs = rs + CC*64;
    const int n   = blockIdx.y;
    const int tv0 = blockIdx.x * 64;
    const int tid = threadIdx.x;

    for (int idx = tid; idx < CC*64; idx += 256) {
        const int c = idx >> 6, col = idx & 63;
        const size_t g = (size_t)n*CTVSZ + (size_t)c*TV + tv0 + col;
        xs[col*K5XSTR + c]      = feat[g];
        xs[col*K5XSTR + 64 + c] = g_msg[g];
    }

    const int og = tid >> 4;
    const int cg = tid & 15;

    for (int pass = 0; pass < 3; pass++) {
        const float* WA = (pass == 0) ? Wir : (pass == 1) ? Wii : Win;
        const float* WB = (pass == 0) ? Whr : (pass == 1) ? Whi : Whh;
        __syncthreads();
        for (int idx = tid; idx < CC*16; idx += 256) {
            const int o = idx >> 4, cq = idx & 15;
            reinterpret_cast<float4*>(ws + o*128)[cq] =
                reinterpret_cast<const float4*>(WA + o*64)[cq];
            reinterpret_cast<float4*>(ws + o*128 + 64)[cq] =
                reinterpret_cast<const float4*>(WB + o*64)[cq];
        }
        __syncthreads();

        if (pass < 2) {
            unsigned long long acc2[4][4];
            #pragma unroll
            for (int i = 0; i < 4; i++)
                #pragma unroll
                for (int q = 0; q < 4; q++) acc2[i][q] = 0ull;
            #pragma unroll 2
            for (int k4 = 0; k4 < 128; k4 += 4) {
                ulonglong2 x[4];
                #pragma unroll
                for (int q = 0; q < 4; q++)
                    x[q] = *reinterpret_cast<const ulonglong2*>(
                               &xs[(cg + 16*q)*K5XSTR + k4]);
                #pragma unroll
                for (int i = 0; i < 4; i++) {
                    const ulonglong2 w = *reinterpret_cast<const ulonglong2*>(
                                             &ws[(og + 16*i)*128 + k4]);
                    #pragma unroll
                    for (int q = 0; q < 4; q++) {
                        ffma2(acc2[i][q], w.x, x[q].x);
                        ffma2(acc2[i][q], w.y, x[q].y);
                    }
                }
            }
            const float* bvec = (pass == 0) ? bir : bii;
            float* gs = (pass == 0) ? rs : zs;
            #pragma unroll
            for (int i = 0; i < 4; i++) {
                const int o = og + 16*i;
                const float bv = bvec[o];
                #pragma unroll
                for (int q = 0; q < 4; q++) {
                    const int col = cg + 16*q;
                    gs[o*64 + col] = 1.f/(1.f + expf(-(f2sum(acc2[i][q]) + bv)));
                }
            }
        } else {
            unsigned long long accA[4][4], accB[4][4];
            #pragma unroll
            for (int i = 0; i < 4; i++)
                #pragma unroll
                for (int q = 0; q < 4; q++) { accA[i][q] = 0ull; accB[i][q] = 0ull; }
            #pragma unroll 2
            for (int k4 = 0; k4 < 64; k4 += 4) {
                ulonglong2 x[4];
                #pragma unroll
                for (int q = 0; q < 4; q++)
                    x[q] = *reinterpret_cast<const ulonglong2*>(
                               &xs[(cg + 16*q)*K5XSTR + k4]);
                #pragma unroll
                for (int i = 0; i < 4; i++) {
                    const ulonglong2 w = *reinterpret_cast<const ulonglong2*>(
                                             &ws[(og + 16*i)*128 + k4]);
                    #pragma unroll
                    for (int q = 0; q < 4; q++) {
                        ffma2(accA[i][q], w.x, x[q].x);
                        ffma2(accA[i][q], w.y, x[q].y);
                    }
                }
            }
            #pragma unroll 2
            for (int k4 = 64; k4 < 128; k4 += 4) {
                ulonglong2 x[4];
                #pragma unroll
                for (int q = 0; q < 4; q++)
                    x[q] = *reinterpret_cast<const ulonglong2*>(
                               &xs[(cg + 16*q)*K5XSTR + k4]);
                #pragma unroll
                for (int i = 0; i < 4; i++) {
                    const ulonglong2 w = *reinterpret_cast<const ulonglong2*>(
                                             &ws[(og + 16*i)*128 + k4]);
                    #pragma unroll
                    for (int q = 0; q < 4; q++) {
                        ffma2(accB[i][q], w.x, x[q].x);
                        ffma2(accB[i][q], w.y, x[q].y);
                    }
                }
            }
            __syncthreads();
            #pragma unroll
            for (int i = 0; i < 4; i++) {
                const int o = og + 16*i;
                const float bv = bin[o];
                #pragma unroll
                for (int q = 0; q < 4; q++) {
                    const int col = cg + 16*q;
                    const float r = rs[o*64 + col];
                    const float z = zs[o*64 + col];
                    const float nn = tanhf(f2sum(accA[i][q]) + bv + r*f2sum(accB[i][q]));
                    const size_t g = (size_t)n*CTVSZ + (size_t)o*TV + tv0 + col;
                    out[g] = (1.f - z)*nn + z*hid[g];
                }
            }
        }
    }
}

// ============================================================
extern "C" void kernel_launch(void* const* d_in, const int* in_sizes, int n_in,
                              void* d_out, int out_size) {
    const float* feature = (const float*)d_in[0];
    const float* hidden  = (const float*)d_in[1];
    const float* A    = (const float*)d_in[2];
    const float* PA   = (const float*)d_in[3];
    const float* caw  = (const float*)d_in[4];
    const float* cab  = (const float*)d_in[5];
    const float* cbw  = (const float*)d_in[6];
    const float* cbb  = (const float*)d_in[7];
    const float* cdw  = (const float*)d_in[8];
    const float* cdb  = (const float*)d_in[9];
    const float* gbn_g = (const float*)d_in[10];
    const float* gbn_b = (const float*)d_in[11];
    const float* gbn_m = (const float*)d_in[12];
    const float* gbn_v = (const float*)d_in[13];
    const float* tcn_w = (const float*)d_in[14];
    const float* tcn_b = (const float*)d_in[15];
    const float* tbn_g = (const float*)d_in[16];
    const float* tbn_b = (const float*)d_in[17];
    const float* tbn_m = (const float*)d_in[18];
    const float* tbn_v = (const float*)d_in[19];

    const float *Wir,*Wii,*Win,*Whr,*Whi,*Whh,*bir,*bii,*bin;
    if (in_sizes[21] == 64) {
        Wir=(const float*)d_in[20]; bir=(const float*)d_in[21];
        Wii=(const float*)d_in[22]; bii=(const float*)d_in[23];
        Win=(const float*)d_in[24]; bin=(const float*)d_in[25];
        Whr=(const float*)d_in[26]; Whi=(const float*)d_in[27]; Whh=(const float*)d_in[28];
    } else {
        Wir=(const float*)d_in[20]; Wii=(const float*)d_in[21]; Win=(const float*)d_in[22];
        Whr=(const float*)d_in[23]; Whi=(const float*)d_in[24]; Whh=(const float*)d_in[25];
        bir=(const float*)d_in[26]; bii=(const float*)d_in[27]; bin=(const float*)d_in[28];
    }
    float* out = (float*)d_out;

    cudaFuncSetAttribute(k2a_score, cudaFuncAttributeMaxDynamicSharedMemorySize, K2A_SMEM);
    cudaFuncSetAttribute(k3_gcn, cudaFuncAttributeMaxDynamicSharedMemorySize, K3_SMEM);
    cudaFuncSetAttribute(k4_tcn, cudaFuncAttributeMaxDynamicSharedMemorySize, K4_SMEM);
    cudaFuncSetAttribute(k5_gru, cudaFuncAttributeMaxDynamicSharedMemorySize, K5_SMEM);

    k1_ab <<<dim3(100, NB), 256>>>(hidden, caw, cab, cbw, cbb, tcn_w);
    k2a_score<<<dim3(NSUB*NB, 8), 800, K2A_SMEM>>>();
    k2b_soft<<<NSUB*NB, 640>>>(A, PA);
    k3_gcn<<<dim3(TV/128, NB), 512, K3_SMEM>>>(hidden, cdw, cdb, gbn_g, gbn_b, gbn_m, gbn_v);
    k4_tcn<<<dim3(TV/K4W, NB), 256, K4_SMEM>>>(hidden, tcn_b, tbn_g, tbn_b, tbn_m, tbn_v);
    k5_gru<<<dim3(100, NB), 256, K5_SMEM>>>(feature, hidden,
                                            Wir, Whr, Wii, Whi, Win, Whh,
                                            bir, bii, bin, out);
    (void)n_in; (void)out_size; (void)in_sizes;
}

// round 16
// speedup vs baseline: 1.0143x; 1.0143x over previous
#include <cuda_runtime.h>
#include <math.h>

#define NB    32
#define CC    64
#define TT    256
#define VV    25
#define ICH   16
#define NSUB  3
#define TV    (TT*VV)      // 6400
#define CTVSZ (CC*TV)      // 409600
#define KATT  (ICH*TT)     // 4096

// -------- scratch (device globals; no allocation) --------
__device__ float g_a[NSUB*NB*ICH*TV];
__device__ float g_b[NSUB*NB*ICH*TV];
__device__ float g_att[NSUB*NB*VV*VV];
__device__ float g_gcn[NB*CTVSZ];
__device__ float g_msg[NB*CTVSZ];
__device__ float g_twT[9*CC*CC];            // tcn weights [kk][o][c] (built in k1)
__device__ float g_wdT[NSUB*CC*CC];         // conv_d weights [s][c][o] (built in k1)
__device__ float g_scorep[NSUB*NB*8*VV*VV]; // split-K partial scores

// -------- packed f32x2 helpers --------
__device__ __forceinline__ void ffma2(unsigned long long &d,
                                      const unsigned long long a,
                                      const unsigned long long b) {
    asm("fma.rn.f32x2 %0, %1, %2, %0;" : "+l"(d) : "l"(a), "l"(b));
}
__device__ __forceinline__ float f2sum(unsigned long long v) {
    return __uint_as_float((unsigned)v) + __uint_as_float((unsigned)(v >> 32));
}
__device__ __forceinline__ unsigned long long fpack2(float x) {
    const unsigned u = __float_as_uint(x);
    return ((unsigned long long)u << 32) | u;
}
__device__ __forceinline__ float f2lo(unsigned long long v) {
    return __uint_as_float((unsigned)v);
}
__device__ __forceinline__ float f2hi(unsigned long long v) {
    return __uint_as_float((unsigned)(v >> 32));
}

// ============================================================
// K1: a = conv_a(h), b = conv_b(h) + side-work: blockIdx.y==0
// blocks build g_twT AND g_wdT (one-off, 492 elems/block).
// ============================================================
__global__ void __launch_bounds__(256) k1_ab(
    const float* __restrict__ h,
    const float* __restrict__ caw, const float* __restrict__ cab,
    const float* __restrict__ cbw, const float* __restrict__ cbb,
    const float* __restrict__ tw,  const float* __restrict__ cdw)
{
    __shared__ float hs[CC*64];
    __shared__ float wgt[96*CC];
    __shared__ float bias[96];
    const int n   = blockIdx.y;
    const int tv0 = blockIdx.x * 64;
    const int tid = threadIdx.x;

    if (n == 0) {
        const int base = blockIdx.x * 492;
        for (int t = tid; t < 492; t += 256) {
            const int idx = base + t;
            if (idx < 9*CC*CC) {
                const int kk = idx / (CC*CC), oc = idx % (CC*CC);
                g_twT[idx] = tw[oc*9 + kk];
            } else if (idx < 12*CC*CC) {
                const int j = idx - 9*CC*CC;
                const int s = j / (CC*CC), oc = j % (CC*CC);
                const int o = oc >> 6, c = oc & 63;
                g_wdT[s*CC*CC + c*CC + o] = cdw[j];
            }
        }
    }

    const float* hb = h + (size_t)n*CTVSZ + tv0;
    for (int idx = tid; idx < CC*16; idx += 256) {
        const int c = idx >> 4, q = idx & 15;
        reinterpret_cast<float4*>(hs)[c*16 + q] =
            reinterpret_cast<const float4*>(hb + (size_t)c*TV)[q];
    }
    for (int idx = tid; idx < 48*CC/4; idx += 256) {
        reinterpret_cast<float4*>(wgt)[idx] = reinterpret_cast<const float4*>(caw)[idx];
        reinterpret_cast<float4*>(wgt + 48*CC)[idx] = reinterpret_cast<const float4*>(cbw)[idx];
    }
    if (tid < 48) { bias[tid] = cab[tid]; bias[48 + tid] = cbb[tid]; }
    __syncthreads();

    const int og = tid >> 4;
    const int cg = tid & 15;
    float acc[6][4];
    #pragma unroll
    for (int i = 0; i < 6; i++)
        #pragma unroll
        for (int j = 0; j < 4; j++) acc[i][j] = 0.f;

    #pragma unroll 4
    for (int c = 0; c < CC; c++) {
        float ir[4], wr[6];
        #pragma unroll
        for (int j = 0; j < 4; j++) ir[j] = hs[c*64 + cg + 16*j];
        #pragma unroll
        for (int i = 0; i < 6; i++) wr[i] = wgt[(og + 16*i)*CC + c];
        #pragma unroll
        for (int i = 0; i < 6; i++)
            #pragma unroll
            for (int j = 0; j < 4; j++) acc[i][j] += wr[i]*ir[j];
    }

    #pragma unroll
    for (int i = 0; i < 6; i++) {
        const int r = og + 16*i;
        const int conv = r / 48;
        const int sic  = r % 48;
        const int s  = sic >> 4;
        const int ic = sic & 15;
        float* dst = conv ? g_b : g_a;
        const size_t base = ((size_t)(s*NB + n)*ICH + ic)*TV + tv0;
        const float bb = bias[r];
        #pragma unroll
        for (int j = 0; j < 4; j++)
            dst[base + cg + 16*j] = acc[i][j] + bb;
    }
}

// ============================================================
// K2a: split-K attention partial scores. grid (96, 8).
// ============================================================
#define K2ASL  512
#define K2ASTR 520
#define K2A_SMEM (2*25*K2ASTR*4)   // 104,000 B

__global__ void __launch_bounds__(800) k2a_score()
{
    extern __shared__ float sm2a[];
    float* sat = sm2a;
    float* sbt = sm2a + 25*K2ASTR;
    const int sn  = blockIdx.x;
    const int sl  = blockIdx.y;
    const int k0  = sl * K2ASL;
    const int tid = threadIdx.x;
    const float* ab  = g_a + (size_t)sn*KATT*VV;
    const float* bbp = g_b + (size_t)sn*KATT*VV;

    for (int idx = tid; idx < K2ASL*VV; idx += 800) {
        const int r = idx / VV, vv = idx - r*VV;
        sat[vv*K2ASTR + r] = ab[(size_t)k0*VV + idx];
        sbt[vv*K2ASTR + r] = bbp[(size_t)k0*VV + idx];
    }
    __syncthreads();

    const int warp = tid >> 5;
    const int lane = tid & 31;
    const int v0 = (warp / 5) * 5;
    const int w0 = (warp % 5) * 5;

    float acc[5][5];
    #pragma unroll
    for (int x = 0; x < 5; x++)
        #pragma unroll
        for (int y = 0; y < 5; y++) acc[x][y] = 0.f;

    #pragma unroll 4
    for (int i = 0; i < K2ASL/32; i++) {
        const int k = lane + 32*i;
        float av[5], bv[5];
        #pragma unroll
        for (int x = 0; x < 5; x++) av[x] = sat[(v0 + x)*K2ASTR + k];
        #pragma unroll
        for (int y = 0; y < 5; y++) bv[y] = sbt[(w0 + y)*K2ASTR + k];
        #pragma unroll
        for (int x = 0; x < 5; x++)
            #pragma unroll
            for (int y = 0; y < 5; y++) acc[x][y] += av[x]*bv[y];
    }

    #pragma unroll
    for (int off = 16; off > 0; off >>= 1)
        #pragma unroll
        for (int x = 0; x < 5; x++)
            #pragma unroll
            for (int y = 0; y < 5; y++)
                acc[x][y] += __shfl_down_sync(0xffffffffu, acc[x][y], off);

    if (lane == 0) {
        float* dst = g_scorep + ((size_t)sn*8 + sl)*VV*VV;
        #pragma unroll
        for (int x = 0; x < 5; x++)
            #pragma unroll
            for (int y = 0; y < 5; y++)
                dst[(v0 + x)*VV + w0 + y] = acc[x][y];
    }
}

// ============================================================
// K2b: reduce split-K partials + softmax + Aeff -> g_att
// ============================================================
__global__ void __launch_bounds__(640) k2b_soft(
    const float* __restrict__ Amat, const float* __restrict__ PA)
{
    __shared__ float score[VV*VV];
    __shared__ float wm[VV], wi[VV];
    const int sn  = blockIdx.x;
    const int tid = threadIdx.x;

    if (tid < VV*VV) {
        const float* sp = g_scorep + (size_t)sn*8*VV*VV + tid;
        float sum = 0.f;
        #pragma unroll
        for (int sl = 0; sl < 8; sl++) sum += sp[sl*VV*VV];
        score[tid] = sum * (1.f/4096.f);
    }
    __syncthreads();

    if (tid < VV) {
        const int ww = tid;
        float m = -1e30f;
        for (int vv = 0; vv < VV; vv++) m = fmaxf(m, score[vv*VV + ww]);
        float sum = 0.f;
        for (int vv = 0; vv < VV; vv++) sum += expf(score[vv*VV + ww] - m);
        wm[ww] = m; wi[ww] = 1.f/sum;
    }
    __syncthreads();

    if (tid < VV*VV) {
        const int vv = tid / VV, ww = tid % VV;
        const int s = sn / NB;
        const float e = expf(score[tid] - wm[ww])*wi[ww]
                      + Amat[(s*VV + vv)*VV + ww] + PA[(s*VV + vv)*VV + ww];
        g_att[(size_t)sn*VV*VV + tid] = e;
    }
}

// ============================================================
// K3 v4: LDS-lean gcn.
// z-phase: thread = (cq, j): one j, 16 c's -> per v: 4 distinct
// LDS.128 + 1 scalar atts for 8 ffma2 (no duplicate loads).
// conv phase: float4 wdT broadcast (restored).
// ============================================================
#define K3HST 68
#define K3HW  175
#define K3_SMEM ((K3HW*K3HST + CC*128 + CC*CC + 640)*4)   // 99,312 B

__global__ void __launch_bounds__(512, 2) k3_gcn(
    const float* __restrict__ h, const float* __restrict__ cdb,
    const float* __restrict__ bng, const float* __restrict__ bnb,
    const float* __restrict__ bnm, const float* __restrict__ bnv)
{
    extern __shared__ float sm3[];
    float* hst  = sm3;                        // [row][c] stride 68
    float* zs   = sm3 + K3HW*K3HST;           // [c][j]  64 x 128
    float* wdT  = zs + CC*128;                // [c][o]
    float* atts = wdT + CC*CC;                // 625
    const int n   = blockIdx.y;
    const int j0  = blockIdx.x * 128;
    const int t0  = j0 / 25;
    const int jwb = t0 * 25;
    const int W   = ((j0 + 127)/25 + 1)*25 - jwb;
    const int tid = threadIdx.x;

    for (int idx = tid; idx < CC*W; idx += 512) {
        const int c = idx / W, r = idx - c*W;
        hst[r*K3HST + c] = h[(size_t)n*CTVSZ + (size_t)c*TV + jwb + r];
    }

    // z-phase decode: thread = (cq 0..3, jz 0..127)
    const int jz  = tid & 127;
    const int cqz = tid >> 7;
    const int c0z = cqz*16;
    const int jgz = j0 + jz;
    const int trz = (jgz/25)*25 - jwb;
    const int wvz = jgz % 25;
    // conv-phase decode (unchanged)
    const int jg = tid & 31;
    const int cg = tid >> 5;

    unsigned long long acc2[4][2];
    #pragma unroll
    for (int i = 0; i < 4; i++) { acc2[i][0] = 0ull; acc2[i][1] = 0ull; }

    for (int s = 0; s < NSUB; s++) {
        __syncthreads();
        for (int idx = tid; idx < VV*VV; idx += 512)
            atts[idx] = g_att[(size_t)(s*NB + n)*VV*VV + idx];
        for (int idx = tid; idx < CC*CC/4; idx += 512)
            reinterpret_cast<float4*>(wdT)[idx] =
                reinterpret_cast<const float4*>(g_wdT + s*CC*CC)[idx];
        __syncthreads();

        // z-phase: zacc[8] over 16 c's for one j
        {
            unsigned long long zacc[8];
            #pragma unroll
            for (int p = 0; p < 8; p++) zacc[p] = 0ull;
            #pragma unroll 5
            for (int v = 0; v < VV; v++) {
                const float* hr = &hst[(trz + v)*K3HST + c0z];
                const ulonglong2 ha = *reinterpret_cast<const ulonglong2*>(hr);
                const ulonglong2 hb = *reinterpret_cast<const ulonglong2*>(hr + 4);
                const ulonglong2 hc = *reinterpret_cast<const ulonglong2*>(hr + 8);
                const ulonglong2 hd = *reinterpret_cast<const ulonglong2*>(hr + 12);
                const unsigned long long a2 = fpack2(atts[v*VV + wvz]);
                ffma2(zacc[0], ha.x, a2); ffma2(zacc[1], ha.y, a2);
                ffma2(zacc[2], hb.x, a2); ffma2(zacc[3], hb.y, a2);
                ffma2(zacc[4], hc.x, a2); ffma2(zacc[5], hc.y, a2);
                ffma2(zacc[6], hd.x, a2); ffma2(zacc[7], hd.y, a2);
            }
            #pragma unroll
            for (int p = 0; p < 8; p++) {
                zs[(c0z + 2*p    )*128 + jz] = f2lo(zacc[p]);
                zs[(c0z + 2*p + 1)*128 + jz] = f2hi(zacc[p]);
            }
        }
        __syncthreads();

        // conv_d: float4 wdT broadcast + packed z
        #pragma unroll 4
        for (int c = 0; c < CC; c++) {
            const ulonglong2 z2 = *reinterpret_cast<const ulonglong2*>(
                                      &zs[c*128 + jg*4]);
            const float4 w4 = *reinterpret_cast<const float4*>(
                                  &wdT[c*CC + cg*4]);
            unsigned long long wp;
            wp = fpack2(w4.x); ffma2(acc2[0][0], z2.x, wp); ffma2(acc2[0][1], z2.y, wp);
            wp = fpack2(w4.y); ffma2(acc2[1][0], z2.x, wp); ffma2(acc2[1][1], z2.y, wp);
            wp = fpack2(w4.z); ffma2(acc2[2][0], z2.x, wp); ffma2(acc2[2][1], z2.y, wp);
            wp = fpack2(w4.w); ffma2(acc2[3][0], z2.x, wp); ffma2(acc2[3][1], z2.y, wp);
        }
    }

    #pragma unroll
    for (int i = 0; i < 4; i++) {
        const int o = cg*4 + i;
        const float scale = bng[o] * rsqrtf(bnv[o] + 1e-5f);
        const float mm = bnm[o], bb = bnb[o];
        const float bsum = cdb[o] + cdb[CC + o] + cdb[2*CC + o];
        float y[4];
        y[0] = f2lo(acc2[i][0]); y[1] = f2hi(acc2[i][0]);
        y[2] = f2lo(acc2[i][1]); y[3] = f2hi(acc2[i][1]);
        float4 outv;
        float* po = &outv.x;
        #pragma unroll
        for (int jj = 0; jj < 4; jj++) {
            const int r = j0 + jg*4 + jj - jwb;
            const float val = (y[jj] + bsum - mm)*scale + bb + hst[r*K3HST + o];
            po[jj] = fmaxf(val, 0.f);
        }
        *reinterpret_cast<float4*>(
            &g_gcn[(size_t)n*CTVSZ + (size_t)o*TV + j0 + jg*4]) = outv;
    }
}

// ============================================================
// K4: tcn with smem weight staging (proven R12 version)
// ============================================================
#define K4W   128
#define K4IN  328
#define K4STR 68
#define K4_SMEM ((K4IN*K4STR + CC*CC)*4)   // 105,600 B

__global__ void __launch_bounds__(256, 2) k4_tcn(
    const float* __restrict__ h,
    const float* __restrict__ tb,
    const float* __restrict__ bng, const float* __restrict__ bnb,
    const float* __restrict__ bnm, const float* __restrict__ bnv)
{
    extern __shared__ float sm4[];
    float* in = sm4;
    float* wk = sm4 + K4IN*K4STR;
    const int n   = blockIdx.y;
    const int tv0 = blockIdx.x * K4W;
    const int tid = threadIdx.x;

    for (int idx = tid; idx < CC*K4IN; idx += 256) {
        const int c = idx / K4IN, j = idx % K4IN;
        const int gtv = tv0 - 100 + j;
        const float v = (gtv >= 0 && gtv < TV)
                        ? g_gcn[(size_t)n*CTVSZ + (size_t)c*TV + gtv] : 0.f;
        in[j*K4STR + c] = v;
    }

    const int og   = tid >> 5;
    const int colg = tid & 31;

    unsigned long long acc2[8][4];
    #pragma unroll
    for (int i = 0; i < 8; i++)
        #pragma unroll
        for (int q = 0; q < 4; q++) acc2[i][q] = 0ull;

    for (int kk = 0; kk < 9; kk++) {
        __syncthreads();
        for (int idx = tid; idx < CC*CC/4; idx += 256)
            reinterpret_cast<float4*>(wk)[idx] =
                reinterpret_cast<const float4*>(g_twT + kk*CC*CC)[idx];
        __syncthreads();

        #pragma unroll 2
        for (int c4 = 0; c4 < CC; c4 += 4) {
            ulonglong2 ir[4];
            #pragma unroll
            for (int q = 0; q < 4; q++)
                ir[q] = *reinterpret_cast<const ulonglong2*>(
                            &in[(colg + 32*q + 25*kk)*K4STR + c4]);
            #pragma unroll
            for (int i = 0; i < 8; i++) {
                const ulonglong2 w = *reinterpret_cast<const ulonglong2*>(
                                         &wk[(og*8 + i)*CC + c4]);
                #pragma unroll
                for (int q = 0; q < 4; q++) {
                    ffma2(acc2[i][q], w.x, ir[q].x);
                    ffma2(acc2[i][q], w.y, ir[q].y);
                }
            }
        }
    }

    #pragma unroll
    for (int i = 0; i < 8; i++) {
        const int o = og*8 + i;
        const float scale = bng[o]*rsqrtf(bnv[o] + 1e-5f);
        const float bbias = tb[o], mm = bnm[o], bb2 = bnb[o];
        #pragma unroll
        for (int q = 0; q < 4; q++) {
            const int col = colg + 32*q;
            float val = (f2sum(acc2[i][q]) + bbias - mm)*scale + bb2;
            val += h[(size_t)n*CTVSZ + (size_t)o*TV + tv0 + col];
            g_msg[(size_t)n*CTVSZ + (size_t)o*TV + tv0 + col] = fmaxf(val, 0.f);
        }
    }
}

// ============================================================
// K5: GRU with smem weight staging (proven R12/R9 version)
// ============================================================
#define K5XSTR 132
#define K5_SMEM ((64*K5XSTR + CC*128 + 2*CC*64)*4)   // 99,328 B

__global__ void __launch_bounds__(256, 2) k5_gru(
    const float* __restrict__ feat, const float* __restrict__ hid,
    const float* __restrict__ Wir, const float* __restrict__ Whr,
    const float* __restrict__ Wii, const float* __restrict__ Whi,
    const float* __restrict__ Win, const float* __restrict__ Whh,
    const float* __restrict__ bir, const float* __restrict__ bii,
    const float* __restrict__ bin, float* __restrict__ out)
{
    extern __shared__ float sm5[];
    float* xs = sm5;
    float* ws = sm5 + 64*K5XSTR;
    float* rs = ws + CC*128;
    float* zs = rs + CC*64;
    const int n   = blockIdx.y;
    const int tv0 = blockIdx.x * 64;
    const int tid = threadIdx.x;

    for (int idx = tid; idx < CC*64; idx += 256) {
        const int c = idx >> 6, col = idx & 63;
        const size_t g = (size_t)n*CTVSZ + (size_t)c*TV + tv0 + col;
        xs[col*K5XSTR + c]      = feat[g];
        xs[col*K5XSTR + 64 + c] = g_msg[g];
    }

    const int og = tid >> 4;
    const int cg = tid & 15;

    for (int pass = 0; pass < 3; pass++) {
        const float* WA = (pass == 0) ? Wir : (pass == 1) ? Wii : Win;
        const float* WB = (pass == 0) ? Whr : (pass == 1) ? Whi : Whh;
        __syncthreads();
        for (int idx = tid; idx < CC*16; idx += 256) {
            const int o = idx >> 4, cq = idx & 15;
            reinterpret_cast<float4*>(ws + o*128)[cq] =
                reinterpret_cast<const float4*>(WA + o*64)[cq];
            reinterpret_cast<float4*>(ws + o*128 + 64)[cq] =
                reinterpret_cast<const float4*>(WB + o*64)[cq];
        }
        __syncthreads();

        if (pass < 2) {
            unsigned long long acc2[4][4];
            #pragma unroll
            for (int i = 0; i < 4; i++)
                #pragma unroll
                for (int q = 0; q < 4; q++) acc2[i][q] = 0ull;
            #pragma unroll 2
            for (int k4 = 0; k4 < 128; k4 += 4) {
                ulonglong2 x[4];
                #pragma unroll
                for (int q = 0; q < 4; q++)
                    x[q] = *reinterpret_cast<const ulonglong2*>(
                               &xs[(cg + 16*q)*K5XSTR + k4]);
                #pragma unroll
                for (int i = 0; i < 4; i++) {
                    const ulonglong2 w = *reinterpret_cast<const ulonglong2*>(
                                             &ws[(og + 16*i)*128 + k4]);
                    #pragma unroll
                    for (int q = 0; q < 4; q++) {
                        ffma2(acc2[i][q], w.x, x[q].x);
                        ffma2(acc2[i][q], w.y, x[q].y);
                    }
                }
            }
            const float* bvec = (pass == 0) ? bir : bii;
            float* gs = (pass == 0) ? rs : zs;
            #pragma unroll
            for (int i = 0; i < 4; i++) {
                const int o = og + 16*i;
                const float bv = bvec[o];
                #pragma unroll
                for (int q = 0; q < 4; q++) {
                    const int col = cg + 16*q;
                    gs[o*64 + col] = 1.f/(1.f + expf(-(f2sum(acc2[i][q]) + bv)));
                }
            }
        } else {
            unsigned long long accA[4][4], accB[4][4];
            #pragma unroll
            for (int i = 0; i < 4; i++)
                #pragma unroll
                for (int q = 0; q < 4; q++) { accA[i][q] = 0ull; accB[i][q] = 0ull; }
            #pragma unroll 2
            for (int k4 = 0; k4 < 64; k4 += 4) {
                ulonglong2 x[4];
                #pragma unroll
                for (int q = 0; q < 4; q++)
                    x[q] = *reinterpret_cast<const ulonglong2*>(
                               &xs[(cg + 16*q)*K5XSTR + k4]);
                #pragma unroll
                for (int i = 0; i < 4; i++) {
                    const ulonglong2 w = *reinterpret_cast<const ulonglong2*>(
                                             &ws[(og + 16*i)*128 + k4]);
                    #pragma unroll
                    for (int q = 0; q < 4; q++) {
                        ffma2(accA[i][q], w.x, x[q].x);
                        ffma2(accA[i][q], w.y, x[q].y);
                    }
                }
            }
            #pragma unroll 2
            for (int k4 = 64; k4 < 128; k4 += 4) {
                ulonglong2 x[4];
                #pragma unroll
                for (int q = 0; q < 4; q++)
                    x[q] = *reinterpret_cast<const ulonglong2*>(
                               &xs[(cg + 16*q)*K5XSTR + k4]);
                #pragma unroll
                for (int i = 0; i < 4; i++) {
                    const ulonglong2 w = *reinterpret_cast<const ulonglong2*>(
                                             &ws[(og + 16*i)*128 + k4]);
                    #pragma unroll
                    for (int q = 0; q < 4; q++) {
                        ffma2(accB[i][q], w.x, x[q].x);
                        ffma2(accB[i][q], w.y, x[q].y);
                    }
                }
            }
            __syncthreads();
            #pragma unroll
            for (int i = 0; i < 4; i++) {
                const int o = og + 16*i;
                const float bv = bin[o];
                #pragma unroll
                for (int q = 0; q < 4; q++) {
                    const int col = cg + 16*q;
                    const float r = rs[o*64 + col];
                    const float z = zs[o*64 + col];
                    const float nn = tanhf(f2sum(accA[i][q]) + bv + r*f2sum(accB[i][q]));
                    const size_t g = (size_t)n*CTVSZ + (size_t)o*TV + tv0 + col;
                    out[g] = (1.f - z)*nn + z*hid[g];
                }
            }
        }
    }
}

// ============================================================
extern "C" void kernel_launch(void* const* d_in, const int* in_sizes, int n_in,
                              void* d_out, int out_size) {
    const float* feature = (const float*)d_in[0];
    const float* hidden  = (const float*)d_in[1];
    const float* A    = (const float*)d_in[2];
    const float* PA   = (const float*)d_in[3];
    const float* caw  = (const float*)d_in[4];
    const float* cab  = (const float*)d_in[5];
    const float* cbw  = (const float*)d_in[6];
    const float* cbb  = (const float*)d_in[7];
    const float* cdw  = (const float*)d_in[8];
    const float* cdb  = (const float*)d_in[9];
    const float* gbn_g = (const float*)d_in[10];
    const float* gbn_b = (const float*)d_in[11];
    const float* gbn_m = (const float*)d_in[12];
    const float* gbn_v = (const float*)d_in[13];
    const float* tcn_w = (const float*)d_in[14];
    const float* tcn_b = (const float*)d_in[15];
    const float* tbn_g = (const float*)d_in[16];
    const float* tbn_b = (const float*)d_in[17];
    const float* tbn_m = (const float*)d_in[18];
    const float* tbn_v = (const float*)d_in[19];

    const float *Wir,*Wii,*Win,*Whr,*Whi,*Whh,*bir,*bii,*bin;
    if (in_sizes[21] == 64) {
        Wir=(const float*)d_in[20]; bir=(const float*)d_in[21];
        Wii=(const float*)d_in[22]; bii=(const float*)d_in[23];
        Win=(const float*)d_in[24]; bin=(const float*)d_in[25];
        Whr=(const float*)d_in[26]; Whi=(const float*)d_in[27]; Whh=(const float*)d_in[28];
    } else {
        Wir=(const float*)d_in[20]; Wii=(const float*)d_in[21]; Win=(const float*)d_in[22];
        Whr=(const float*)d_in[23]; Whi=(const float*)d_in[24]; Whh=(const float*)d_in[25];
        bir=(const float*)d_in[26]; bii=(const float*)d_in[27]; bin=(const float*)d_in[28];
    }
    float* out = (float*)d_out;

    cudaFuncSetAttribute(k2a_score, cudaFuncAttributeMaxDynamicSharedMemorySize, K2A_SMEM);
    cudaFuncSetAttribute(k3_gcn, cudaFuncAttributeMaxDynamicSharedMemorySize, K3_SMEM);
    cudaFuncSetAttribute(k4_tcn, cudaFuncAttributeMaxDynamicSharedMemorySize, K4_SMEM);
    cudaFuncSetAttribute(k5_gru, cudaFuncAttributeMaxDynamicSharedMemorySize, K5_SMEM);

    k1_ab <<<dim3(100, NB), 256>>>(hidden, caw, cab, cbw, cbb, tcn_w, cdw);
    k2a_score<<<dim3(NSUB*NB, 8), 800, K2A_SMEM>>>();
    k2b_soft<<<NSUB*NB, 640>>>(A, PA);
    k3_gcn<<<dim3(TV/128, NB), 512, K3_SMEM>>>(hidden, cdb, gbn_g, gbn_b, gbn_m, gbn_v);
    k4_tcn<<<dim3(TV/K4W, NB), 256, K4_SMEM>>>(hidden, tcn_b, tbn_g, tbn_b, tbn_m, tbn_v);
    k5_gru<<<dim3(100, NB), 256, K5_SMEM>>>(feature, hidden,
                                            Wir, Whr, Wii, Whi, Win, Whh,
                                            bir, bii, bin, out);
    (void)n_in; (void)out_size; (void)in_sizes;
}

// round 17
// speedup vs baseline: 1.0365x; 1.0219x over previous
#include <cuda_runtime.h>
#include <math.h>

#define NB    32
#define CC    64
#define TT    256
#define VV    25
#define ICH   16
#define NSUB  3
#define TV    (TT*VV)      // 6400
#define CTVSZ (CC*TV)      // 409600
#define KATT  (ICH*TT)     // 4096

// -------- scratch (device globals; no allocation) --------
__device__ float g_a[NSUB*NB*ICH*TV];
__device__ float g_b[NSUB*NB*ICH*TV];
__device__ float g_att[NSUB*NB*VV*VV];
__device__ float g_gcn[NB*CTVSZ];
__device__ float g_msg[NB*CTVSZ];
__device__ float g_twT[9*CC*CC];            // tcn weights [kk][o][c] (built in k1)
__device__ float g_wdT[NSUB*CC*CC];         // conv_d weights [s][c][o] (built in k1)
__device__ float g_scorep[NSUB*NB*8*VV*VV]; // split-K partial scores

// -------- packed f32x2 helpers --------
__device__ __forceinline__ void ffma2(unsigned long long &d,
                                      const unsigned long long a,
                                      const unsigned long long b) {
    asm("fma.rn.f32x2 %0, %1, %2, %0;" : "+l"(d) : "l"(a), "l"(b));
}
__device__ __forceinline__ float f2sum(unsigned long long v) {
    return __uint_as_float((unsigned)v) + __uint_as_float((unsigned)(v >> 32));
}
__device__ __forceinline__ unsigned long long fpack2(float x) {
    const unsigned u = __float_as_uint(x);
    return ((unsigned long long)u << 32) | u;
}
__device__ __forceinline__ float f2lo(unsigned long long v) {
    return __uint_as_float((unsigned)v);
}
__device__ __forceinline__ float f2hi(unsigned long long v) {
    return __uint_as_float((unsigned)(v >> 32));
}

// ============================================================
// K1: a = conv_a(h), b = conv_b(h) + side-work: blockIdx.y==0
// blocks build g_twT AND g_wdT (one-off, 492 elems/block).
// ============================================================
__global__ void __launch_bounds__(256) k1_ab(
    const float* __restrict__ h,
    const float* __restrict__ caw, const float* __restrict__ cab,
    const float* __restrict__ cbw, const float* __restrict__ cbb,
    const float* __restrict__ tw,  const float* __restrict__ cdw)
{
    __shared__ float hs[CC*64];
    __shared__ float wgt[96*CC];
    __shared__ float bias[96];
    const int n   = blockIdx.y;
    const int tv0 = blockIdx.x * 64;
    const int tid = threadIdx.x;

    if (n == 0) {
        const int base = blockIdx.x * 492;
        for (int t = tid; t < 492; t += 256) {
            const int idx = base + t;
            if (idx < 9*CC*CC) {
                const int kk = idx / (CC*CC), oc = idx % (CC*CC);
                g_twT[idx] = tw[oc*9 + kk];
            } else if (idx < 12*CC*CC) {
                const int j = idx - 9*CC*CC;
                const int s = j / (CC*CC), oc = j % (CC*CC);
                const int o = oc >> 6, c = oc & 63;
                g_wdT[s*CC*CC + c*CC + o] = cdw[j];
            }
        }
    }

    const float* hb = h + (size_t)n*CTVSZ + tv0;
    for (int idx = tid; idx < CC*16; idx += 256) {
        const int c = idx >> 4, q = idx & 15;
        reinterpret_cast<float4*>(hs)[c*16 + q] =
            reinterpret_cast<const float4*>(hb + (size_t)c*TV)[q];
    }
    for (int idx = tid; idx < 48*CC/4; idx += 256) {
        reinterpret_cast<float4*>(wgt)[idx] = reinterpret_cast<const float4*>(caw)[idx];
        reinterpret_cast<float4*>(wgt + 48*CC)[idx] = reinterpret_cast<const float4*>(cbw)[idx];
    }
    if (tid < 48) { bias[tid] = cab[tid]; bias[48 + tid] = cbb[tid]; }
    __syncthreads();

    const int og = tid >> 4;
    const int cg = tid & 15;
    float acc[6][4];
    #pragma unroll
    for (int i = 0; i < 6; i++)
        #pragma unroll
        for (int j = 0; j < 4; j++) acc[i][j] = 0.f;

    #pragma unroll 4
    for (int c = 0; c < CC; c++) {
        float ir[4], wr[6];
        #pragma unroll
        for (int j = 0; j < 4; j++) ir[j] = hs[c*64 + cg + 16*j];
        #pragma unroll
        for (int i = 0; i < 6; i++) wr[i] = wgt[(og + 16*i)*CC + c];
        #pragma unroll
        for (int i = 0; i < 6; i++)
            #pragma unroll
            for (int j = 0; j < 4; j++) acc[i][j] += wr[i]*ir[j];
    }

    #pragma unroll
    for (int i = 0; i < 6; i++) {
        const int r = og + 16*i;
        const int conv = r / 48;
        const int sic  = r % 48;
        const int s  = sic >> 4;
        const int ic = sic & 15;
        float* dst = conv ? g_b : g_a;
        const size_t base = ((size_t)(s*NB + n)*ICH + ic)*TV + tv0;
        const float bb = bias[r];
        #pragma unroll
        for (int j = 0; j < 4; j++)
            dst[base + cg + 16*j] = acc[i][j] + bb;
    }
}

// ============================================================
// K2a: split-K attention partial scores. grid (96, 8).
// ============================================================
#define K2ASL  512
#define K2ASTR 520
#define K2A_SMEM (2*25*K2ASTR*4)   // 104,000 B

__global__ void __launch_bounds__(800) k2a_score()
{
    extern __shared__ float sm2a[];
    float* sat = sm2a;
    float* sbt = sm2a + 25*K2ASTR;
    const int sn  = blockIdx.x;
    const int sl  = blockIdx.y;
    const int k0  = sl * K2ASL;
    const int tid = threadIdx.x;
    const float* ab  = g_a + (size_t)sn*KATT*VV;
    const float* bbp = g_b + (size_t)sn*KATT*VV;

    for (int idx = tid; idx < K2ASL*VV; idx += 800) {
        const int r = idx / VV, vv = idx - r*VV;
        sat[vv*K2ASTR + r] = ab[(size_t)k0*VV + idx];
        sbt[vv*K2ASTR + r] = bbp[(size_t)k0*VV + idx];
    }
    __syncthreads();

    const int warp = tid >> 5;
    const int lane = tid & 31;
    const int v0 = (warp / 5) * 5;
    const int w0 = (warp % 5) * 5;

    float acc[5][5];
    #pragma unroll
    for (int x = 0; x < 5; x++)
        #pragma unroll
        for (int y = 0; y < 5; y++) acc[x][y] = 0.f;

    #pragma unroll 4
    for (int i = 0; i < K2ASL/32; i++) {
        const int k = lane + 32*i;
        float av[5], bv[5];
        #pragma unroll
        for (int x = 0; x < 5; x++) av[x] = sat[(v0 + x)*K2ASTR + k];
        #pragma unroll
        for (int y = 0; y < 5; y++) bv[y] = sbt[(w0 + y)*K2ASTR + k];
        #pragma unroll
        for (int x = 0; x < 5; x++)
            #pragma unroll
            for (int y = 0; y < 5; y++) acc[x][y] += av[x]*bv[y];
    }

    #pragma unroll
    for (int off = 16; off > 0; off >>= 1)
        #pragma unroll
        for (int x = 0; x < 5; x++)
            #pragma unroll
            for (int y = 0; y < 5; y++)
                acc[x][y] += __shfl_down_sync(0xffffffffu, acc[x][y], off);

    if (lane == 0) {
        float* dst = g_scorep + ((size_t)sn*8 + sl)*VV*VV;
        #pragma unroll
        for (int x = 0; x < 5; x++)
            #pragma unroll
            for (int y = 0; y < 5; y++)
                dst[(v0 + x)*VV + w0 + y] = acc[x][y];
    }
}

// ============================================================
// K2b: reduce split-K partials + softmax + Aeff -> g_att
// ============================================================
__global__ void __launch_bounds__(640) k2b_soft(
    const float* __restrict__ Amat, const float* __restrict__ PA)
{
    __shared__ float score[VV*VV];
    __shared__ float wm[VV], wi[VV];
    const int sn  = blockIdx.x;
    const int tid = threadIdx.x;

    if (tid < VV*VV) {
        const float* sp = g_scorep + (size_t)sn*8*VV*VV + tid;
        float sum = 0.f;
        #pragma unroll
        for (int sl = 0; sl < 8; sl++) sum += sp[sl*VV*VV];
        score[tid] = sum * (1.f/4096.f);
    }
    __syncthreads();

    if (tid < VV) {
        const int ww = tid;
        float m = -1e30f;
        for (int vv = 0; vv < VV; vv++) m = fmaxf(m, score[vv*VV + ww]);
        float sum = 0.f;
        for (int vv = 0; vv < VV; vv++) sum += expf(score[vv*VV + ww] - m);
        wm[ww] = m; wi[ww] = 1.f/sum;
    }
    __syncthreads();

    if (tid < VV*VV) {
        const int vv = tid / VV, ww = tid % VV;
        const int s = sn / NB;
        const float e = expf(score[tid] - wm[ww])*wi[ww]
                      + Amat[(s*VV + vv)*VV + ww] + PA[(s*VV + vv)*VV + ww];
        g_att[(size_t)sn*VV*VV + tid] = e;
    }
}

// ============================================================
// K3 v5: gcn. z-phase as v4 (thread = (cq, j), no dup loads).
// conv phase remapped: thread = (og2 0..7 -> 8 o's, jp 0..63 ->
// one j-pair): per c: 1 LDS.64 z + 2 broadcast LDS.128 w for
// 8 ffma2 (0.5 wf/ffma2, was 0.625). accs 8 ull (16 regs, same).
// ============================================================
#define K3HST 68
#define K3HW  175
#define K3_SMEM ((K3HW*K3HST + CC*128 + CC*CC + 640)*4)   // 99,312 B

__global__ void __launch_bounds__(512, 2) k3_gcn(
    const float* __restrict__ h, const float* __restrict__ cdb,
    const float* __restrict__ bng, const float* __restrict__ bnb,
    const float* __restrict__ bnm, const float* __restrict__ bnv)
{
    extern __shared__ float sm3[];
    float* hst  = sm3;                        // [row][c] stride 68
    float* zs   = sm3 + K3HW*K3HST;           // [c][j]  64 x 128
    float* wdT  = zs + CC*128;                // [c][o]
    float* atts = wdT + CC*CC;                // 625
    const int n   = blockIdx.y;
    const int j0  = blockIdx.x * 128;
    const int t0  = j0 / 25;
    const int jwb = t0 * 25;
    const int W   = ((j0 + 127)/25 + 1)*25 - jwb;
    const int tid = threadIdx.x;

    for (int idx = tid; idx < CC*W; idx += 512) {
        const int c = idx / W, r = idx - c*W;
        hst[r*K3HST + c] = h[(size_t)n*CTVSZ + (size_t)c*TV + jwb + r];
    }

    // z-phase decode: thread = (cq 0..3, jz 0..127)
    const int jz  = tid & 127;
    const int cqz = tid >> 7;
    const int c0z = cqz*16;
    const int jgz = j0 + jz;
    const int trz = (jgz/25)*25 - jwb;
    const int wvz = jgz % 25;
    // conv-phase decode: thread = (og2 0..7, jp 0..63)
    const int og2 = tid >> 6;     // 8 o's: o = og2*8 + i
    const int jp  = tid & 63;     // j-pair: j = jp*2, jp*2+1

    unsigned long long acc2[8];   // [o], each holds j-pair
    #pragma unroll
    for (int i = 0; i < 8; i++) acc2[i] = 0ull;

    for (int s = 0; s < NSUB; s++) {
        __syncthreads();
        for (int idx = tid; idx < VV*VV; idx += 512)
            atts[idx] = g_att[(size_t)(s*NB + n)*VV*VV + idx];
        for (int idx = tid; idx < CC*CC/4; idx += 512)
            reinterpret_cast<float4*>(wdT)[idx] =
                reinterpret_cast<const float4*>(g_wdT + s*CC*CC)[idx];
        __syncthreads();

        // z-phase: zacc[8] over 16 c's for one j
        {
            unsigned long long zacc[8];
            #pragma unroll
            for (int p = 0; p < 8; p++) zacc[p] = 0ull;
            #pragma unroll 5
            for (int v = 0; v < VV; v++) {
                const float* hr = &hst[(trz + v)*K3HST + c0z];
                const ulonglong2 ha = *reinterpret_cast<const ulonglong2*>(hr);
                const ulonglong2 hb = *reinterpret_cast<const ulonglong2*>(hr + 4);
                const ulonglong2 hc = *reinterpret_cast<const ulonglong2*>(hr + 8);
                const ulonglong2 hd = *reinterpret_cast<const ulonglong2*>(hr + 12);
                const unsigned long long a2 = fpack2(atts[v*VV + wvz]);
                ffma2(zacc[0], ha.x, a2); ffma2(zacc[1], ha.y, a2);
                ffma2(zacc[2], hb.x, a2); ffma2(zacc[3], hb.y, a2);
                ffma2(zacc[4], hc.x, a2); ffma2(zacc[5], hc.y, a2);
                ffma2(zacc[6], hd.x, a2); ffma2(zacc[7], hd.y, a2);
            }
            #pragma unroll
            for (int p = 0; p < 8; p++) {
                zs[(c0z + 2*p    )*128 + jz] = f2lo(zacc[p]);
                zs[(c0z + 2*p + 1)*128 + jz] = f2hi(zacc[p]);
            }
        }
        __syncthreads();

        // conv_d: per c: 1 LDS.64 z-pair + 2 broadcast LDS.128 (8 w)
        #pragma unroll 4
        for (int c = 0; c < CC; c++) {
            const unsigned long long z2 =
                *reinterpret_cast<const unsigned long long*>(&zs[c*128 + jp*2]);
            const float4 wA = *reinterpret_cast<const float4*>(&wdT[c*CC + og2*8]);
            const float4 wB = *reinterpret_cast<const float4*>(&wdT[c*CC + og2*8 + 4]);
            ffma2(acc2[0], z2, fpack2(wA.x));
            ffma2(acc2[1], z2, fpack2(wA.y));
            ffma2(acc2[2], z2, fpack2(wA.z));
            ffma2(acc2[3], z2, fpack2(wA.w));
            ffma2(acc2[4], z2, fpack2(wB.x));
            ffma2(acc2[5], z2, fpack2(wB.y));
            ffma2(acc2[6], z2, fpack2(wB.z));
            ffma2(acc2[7], z2, fpack2(wB.w));
        }
    }

    // epilogue: 8 o's x one j-pair
    {
        const int jA = j0 + jp*2;
        const int rA = jA - jwb;        // rows for residual (consecutive)
        #pragma unroll
        for (int i = 0; i < 8; i++) {
            const int o = og2*8 + i;
            const float scale = bng[o] * rsqrtf(bnv[o] + 1e-5f);
            const float mm = bnm[o], bb = bnb[o];
            const float bsum = cdb[o] + cdb[CC + o] + cdb[2*CC + o];
            float2 ov;
            ov.x = fmaxf((f2lo(acc2[i]) + bsum - mm)*scale + bb
                         + hst[rA*K3HST + o], 0.f);
            ov.y = fmaxf((f2hi(acc2[i]) + bsum - mm)*scale + bb
                         + hst[(rA+1)*K3HST + o], 0.f);
            *reinterpret_cast<float2*>(
                &g_gcn[(size_t)n*CTVSZ + (size_t)o*TV + jA]) = ov;
        }
    }
}

// ============================================================
// K4: tcn with smem weight staging (proven R12 version)
// ============================================================
#define K4W   128
#define K4IN  328
#define K4STR 68
#define K4_SMEM ((K4IN*K4STR + CC*CC)*4)   // 105,600 B

__global__ void __launch_bounds__(256, 2) k4_tcn(
    const float* __restrict__ h,
    const float* __restrict__ tb,
    const float* __restrict__ bng, const float* __restrict__ bnb,
    const float* __restrict__ bnm, const float* __restrict__ bnv)
{
    extern __shared__ float sm4[];
    float* in = sm4;
    float* wk = sm4 + K4IN*K4STR;
    const int n   = blockIdx.y;
    const int tv0 = blockIdx.x * K4W;
    const int tid = threadIdx.x;

    for (int idx = tid; idx < CC*K4IN; idx += 256) {
        const int c = idx / K4IN, j = idx % K4IN;
        const int gtv = tv0 - 100 + j;
        const float v = (gtv >= 0 && gtv < TV)
                        ? g_gcn[(size_t)n*CTVSZ + (size_t)c*TV + gtv] : 0.f;
        in[j*K4STR + c] = v;
    }

    const int og   = tid >> 5;
    const int colg = tid & 31;

    unsigned long long acc2[8][4];
    #pragma unroll
    for (int i = 0; i < 8; i++)
        #pragma unroll
        for (int q = 0; q < 4; q++) acc2[i][q] = 0ull;

    for (int kk = 0; kk < 9; kk++) {
        __syncthreads();
        for (int idx = tid; idx < CC*CC/4; idx += 256)
            reinterpret_cast<float4*>(wk)[idx] =
                reinterpret_cast<const float4*>(g_twT + kk*CC*CC)[idx];
        __syncthreads();

        #pragma unroll 2
        for (int c4 = 0; c4 < CC; c4 += 4) {
            ulonglong2 ir[4];
            #pragma unroll
            for (int q = 0; q < 4; q++)
                ir[q] = *reinterpret_cast<const ulonglong2*>(
                            &in[(colg + 32*q + 25*kk)*K4STR + c4]);
            #pragma unroll
            for (int i = 0; i < 8; i++) {
                const ulonglong2 w = *reinterpret_cast<const ulonglong2*>(
                                         &wk[(og*8 + i)*CC + c4]);
                #pragma unroll
                for (int q = 0; q < 4; q++) {
                    ffma2(acc2[i][q], w.x, ir[q].x);
                    ffma2(acc2[i][q], w.y, ir[q].y);
                }
            }
        }
    }

    #pragma unroll
    for (int i = 0; i < 8; i++) {
        const int o = og*8 + i;
        const float scale = bng[o]*rsqrtf(bnv[o] + 1e-5f);
        const float bbias = tb[o], mm = bnm[o], bb2 = bnb[o];
        #pragma unroll
        for (int q = 0; q < 4; q++) {
            const int col = colg + 32*q;
            float val = (f2sum(acc2[i][q]) + bbias - mm)*scale + bb2;
            val += h[(size_t)n*CTVSZ + (size_t)o*TV + tv0 + col];
            g_msg[(size_t)n*CTVSZ + (size_t)o*TV + tv0 + col] = fmaxf(val, 0.f);
        }
    }
}

// ============================================================
// K5: GRU with smem weight staging (proven R12/R9 version)
// ============================================================
#define K5XSTR 132
#define K5_SMEM ((64*K5XSTR + CC*128 + 2*CC*64)*4)   // 99,328 B

__global__ void __launch_bounds__(256, 2) k5_gru(
    const float* __restrict__ feat, const float* __restrict__ hid,
    const float* __restrict__ Wir, const float* __restrict__ Whr,
    const float* __restrict__ Wii, const float* __restrict__ Whi,
    const float* __restrict__ Win, const float* __restrict__ Whh,
    const float* __restrict__ bir, const float* __restrict__ bii,
    const float* __restrict__ bin, float* __restrict__ out)
{
    extern __shared__ float sm5[];
    float* xs = sm5;
    float* ws = sm5 + 64*K5XSTR;
    float* rs = ws + CC*128;
    float* zs = rs + CC*64;
    const int n   = blockIdx.y;
    const int tv0 = blockIdx.x * 64;
    const int tid = threadIdx.x;

    for (int idx = tid; idx < CC*64; idx += 256) {
        const int c = idx >> 6, col = idx & 63;
        const size_t g = (size_t)n*CTVSZ + (size_t)c*TV + tv0 + col;
        xs[col*K5XSTR + c]      = feat[g];
        xs[col*K5XSTR + 64 + c] = g_msg[g];
    }

    const int og = tid >> 4;
    const int cg = tid & 15;

    for (int pass = 0; pass < 3; pass++) {
        const float* WA = (pass == 0) ? Wir : (pass == 1) ? Wii : Win;
        const float* WB = (pass == 0) ? Whr : (pass == 1) ? Whi : Whh;
        __syncthreads();
        for (int idx = tid; idx < CC*16; idx += 256) {
            const int o = idx >> 4, cq = idx & 15;
            reinterpret_cast<float4*>(ws + o*128)[cq] =
                reinterpret_cast<const float4*>(WA + o*64)[cq];
            reinterpret_cast<float4*>(ws + o*128 + 64)[cq] =
                reinterpret_cast<const float4*>(WB + o*64)[cq];
        }
        __syncthreads();

        if (pass < 2) {
            unsigned long long acc2[4][4];
            #pragma unroll
            for (int i = 0; i < 4; i++)
                #pragma unroll
                for (int q = 0; q < 4; q++) acc2[i][q] = 0ull;
            #pragma unroll 2
            for (int k4 = 0; k4 < 128; k4 += 4) {
                ulonglong2 x[4];
                #pragma unroll
                for (int q = 0; q < 4; q++)
                    x[q] = *reinterpret_cast<const ulonglong2*>(
                               &xs[(cg + 16*q)*K5XSTR + k4]);
                #pragma unroll
                for (int i = 0; i < 4; i++) {
                    const ulonglong2 w = *reinterpret_cast<const ulonglong2*>(
                                             &ws[(og + 16*i)*128 + k4]);
                    #pragma unroll
                    for (int q = 0; q < 4; q++) {
                        ffma2(acc2[i][q], w.x, x[q].x);
                        ffma2(acc2[i][q], w.y, x[q].y);
                    }
                }
            }
            const float* bvec = (pass == 0) ? bir : bii;
            float* gs = (pass == 0) ? rs : zs;
            #pragma unroll
            for (int i = 0; i < 4; i++) {
                const int o = og + 16*i;
                const float bv = bvec[o];
                #pragma unroll
                for (int q = 0; q < 4; q++) {
                    const int col = cg + 16*q;
                    gs[o*64 + col] = 1.f/(1.f + expf(-(f2sum(acc2[i][q]) + bv)));
                }
            }
        } else {
            unsigned long long accA[4][4], accB[4][4];
            #pragma unroll
            for (int i = 0; i < 4; i++)
                #pragma unroll
                for (int q = 0; q < 4; q++) { accA[i][q] = 0ull; accB[i][q] = 0ull; }
            #pragma unroll 2
            for (int k4 = 0; k4 < 64; k4 += 4) {
                ulonglong2 x[4];
                #pragma unroll
                for (int q = 0; q < 4; q++)
                    x[q] = *reinterpret_cast<const ulonglong2*>(
                               &xs[(cg + 16*q)*K5XSTR + k4]);
                #pragma unroll
                for (int i = 0; i < 4; i++) {
                    const ulonglong2 w = *reinterpret_cast<const ulonglong2*>(
                                             &ws[(og + 16*i)*128 + k4]);
                    #pragma unroll
                    for (int q = 0; q < 4; q++) {
                        ffma2(accA[i][q], w.x, x[q].x);
                        ffma2(accA[i][q], w.y, x[q].y);
                    }
                }
            }
            #pragma unroll 2
            for (int k4 = 64; k4 < 128; k4 += 4) {
                ulonglong2 x[4];
                #pragma unroll
                for (int q = 0; q < 4; q++)
                    x[q] = *reinterpret_cast<const ulonglong2*>(
                               &xs[(cg + 16*q)*K5XSTR + k4]);
                #pragma unroll
                for (int i = 0; i < 4; i++) {
                    const ulonglong2 w = *reinterpret_cast<const ulonglong2*>(
                                             &ws[(og + 16*i)*128 + k4]);
                    #pragma unroll
                    for (int q = 0; q < 4; q++) {
                        ffma2(accB[i][q], w.x, x[q].x);
                        ffma2(accB[i][q], w.y, x[q].y);
                    }
                }
            }
            __syncthreads();
            #pragma unroll
            for (int i = 0; i < 4; i++) {
                const int o = og + 16*i;
                const float bv = bin[o];
                #pragma unroll
                for (int q = 0; q < 4; q++) {
                    const int col = cg + 16*q;
                    const float r = rs[o*64 + col];
                    const float z = zs[o*64 + col];
                    const float nn = tanhf(f2sum(accA[i][q]) + bv + r*f2sum(accB[i][q]));
                    const size_t g = (size_t)n*CTVSZ + (size_t)o*TV + tv0 + col;
                    out[g] = (1.f - z)*nn + z*hid[g];
                }
            }
        }
    }
}

// ============================================================
extern "C" void kernel_launch(void* const* d_in, const int* in_sizes, int n_in,
                              void* d_out, int out_size) {
    const float* feature = (const float*)d_in[0];
    const float* hidden  = (const float*)d_in[1];
    const float* A    = (const float*)d_in[2];
    const float* PA   = (const float*)d_in[3];
    const float* caw  = (const float*)d_in[4];
    const float* cab  = (const float*)d_in[5];
    const float* cbw  = (const float*)d_in[6];
    const float* cbb  = (const float*)d_in[7];
    const float* cdw  = (const float*)d_in[8];
    const float* cdb  = (const float*)d_in[9];
    const float* gbn_g = (const float*)d_in[10];
    const float* gbn_b = (const float*)d_in[11];
    const float* gbn_m = (const float*)d_in[12];
    const float* gbn_v = (const float*)d_in[13];
    const float* tcn_w = (const float*)d_in[14];
    const float* tcn_b = (const float*)d_in[15];
    const float* tbn_g = (const float*)d_in[16];
    const float* tbn_b = (const float*)d_in[17];
    const float* tbn_m = (const float*)d_in[18];
    const float* tbn_v = (const float*)d_in[19];

    const float *Wir,*Wii,*Win,*Whr,*Whi,*Whh,*bir,*bii,*bin;
    if (in_sizes[21] == 64) {
        Wir=(const float*)d_in[20]; bir=(const float*)d_in[21];
        Wii=(const float*)d_in[22]; bii=(const float*)d_in[23];
        Win=(const float*)d_in[24]; bin=(const float*)d_in[25];
        Whr=(const float*)d_in[26]; Whi=(const float*)d_in[27]; Whh=(const float*)d_in[28];
    } else {
        Wir=(const float*)d_in[20]; Wii=(const float*)d_in[21]; Win=(const float*)d_in[22];
        Whr=(const float*)d_in[23]; Whi=(const float*)d_in[24]; Whh=(const float*)d_in[25];
        bir=(const float*)d_in[26]; bii=(const float*)d_in[27]; bin=(const float*)d_in[28];
    }
    float* out = (float*)d_out;

    cudaFuncSetAttribute(k2a_score, cudaFuncAttributeMaxDynamicSharedMemorySize, K2A_SMEM);
    cudaFuncSetAttribute(k3_gcn, cudaFuncAttributeMaxDynamicSharedMemorySize, K3_SMEM);
    cudaFuncSetAttribute(k4_tcn, cudaFuncAttributeMaxDynamicSharedMemorySize, K4_SMEM);
    cudaFuncSetAttribute(k5_gru, cudaFuncAttributeMaxDynamicSharedMemorySize, K5_SMEM);

    k1_ab <<<dim3(100, NB), 256>>>(hidden, caw, cab, cbw, cbb, tcn_w, cdw);
    k2a_score<<<dim3(NSUB*NB, 8), 800, K2A_SMEM>>>();
    k2b_soft<<<NSUB*NB, 640>>>(A, PA);
    k3_gcn<<<dim3(TV/128, NB), 512, K3_SMEM>>>(hidden, cdb, gbn_g, gbn_b, gbn_m, gbn_v);
    k4_tcn<<<dim3(TV/K4W, NB), 256, K4_SMEM>>>(hidden, tcn_b, tbn_g, tbn_b, tbn_m, tbn_v);
    k5_gru<<<dim3(100, NB), 256, K5_SMEM>>>(feature, hidden,
                                            Wir, Whr, Wii, Whi, Win, Whh,
                                            bir, bii, bin, out);
    (void)n_in; (void)out_size; (void)in_sizes;
}